// round 9
// baseline (speedup 1.0000x reference)
#include <cuda_runtime.h>
#include <cuda_bf16.h>
#include <cstdint>

#define NROWS   32768
#define KCODES  8192
#define DIM     256
#define KPACK   768            // 3 * DIM (hi|hi|lo vs hi|lo|hi)
#define DECAY_F 0.99f
#define OMD_F   0.01f
#define EPSV    1e-5f
#define CCOST   0.25f

// output layout (flattened, reference return order, all f32)
#define ZQ_OFF    0
#define LOSS_OFF  8388608
#define IDX_OFF   8388609
#define NEMB_OFF  8421377
#define NCS_OFF   10518529
#define NEMAW_OFF 10526721

// ---------------- scratch (static device globals; no allocs) ----------------
__device__ unsigned long long g_keys[NROWS];
__device__ float g_h[KCODES];
__device__ float g_counts[KCODES];
__device__ float g_dw[KCODES * DIM];
__device__ float g_loss_sum;
__device__ float g_n_tot;
// packed bf16 split operands (K-concatenated)
__device__ __nv_bfloat16 g_A[NROWS * KPACK];    // [z_hi | z_hi | z_lo]
__device__ __nv_bfloat16 g_B[KCODES * KPACK];   // [e_hi | e_lo | e_hi]

// ---------------- helpers ----------------
__device__ __forceinline__ unsigned int fkey(float f) {
    unsigned int u = __float_as_uint(f);
    return (u & 0x80000000u) ? ~u : (u | 0x80000000u);
}
__device__ __forceinline__ unsigned long long ullmin2(unsigned long long a,
                                                      unsigned long long b) {
    return a < b ? a : b;
}
__device__ __forceinline__ uint32_t smem_u32(const void* p) {
    uint32_t a;
    asm("{ .reg .u64 t; cvta.to.shared.u64 t, %1; cvt.u32.u64 %0, t; }"
        : "=r"(a) : "l"(p));
    return a;
}
__device__ __forceinline__ void cp_async16(uint32_t smem, const void* g) {
    asm volatile("cp.async.cg.shared.global [%0], [%1], 16;"
                 :: "r"(smem), "l"(g));
}
__device__ __forceinline__ void cp_commit() {
    asm volatile("cp.async.commit_group;");
}
__device__ __forceinline__ void cp_wait1() {
    asm volatile("cp.async.wait_group 1;");
}
__device__ __forceinline__ void ldsm4(uint32_t& r0, uint32_t& r1, uint32_t& r2,
                                      uint32_t& r3, uint32_t addr) {
    asm volatile("ldmatrix.sync.aligned.m8n8.x4.shared.b16 {%0,%1,%2,%3}, [%4];"
                 : "=r"(r0), "=r"(r1), "=r"(r2), "=r"(r3) : "r"(addr));
}
__device__ __forceinline__ void mma16816(float& c0, float& c1, float& c2, float& c3,
                                         uint32_t a0, uint32_t a1, uint32_t a2,
                                         uint32_t a3, uint32_t b0, uint32_t b1) {
    asm volatile(
        "mma.sync.aligned.m16n8k16.row.col.f32.bf16.bf16.f32 "
        "{%0,%1,%2,%3}, {%4,%5,%6,%7}, {%8,%9}, {%0,%1,%2,%3};"
        : "+f"(c0), "+f"(c1), "+f"(c2), "+f"(c3)
        : "r"(a0), "r"(a1), "r"(a2), "r"(a3), "r"(b0), "r"(b1));
}

// ---------------- K0: zero scratch ----------------
__global__ void init_kernel() {
    int i = blockIdx.x * blockDim.x + threadIdx.x;
    if (i < KCODES * DIM) g_dw[i] = 0.0f;
    if (i < NROWS) g_keys[i] = 0xFFFFFFFFFFFFFFFFull;
    if (i < KCODES) g_counts[i] = 0.0f;
    if (i == 0) g_loss_sum = 0.0f;
}

// ---------------- K0b: bf16 hi/lo split + K-concat pack -------------------
__global__ void pack_z_kernel(const float* __restrict__ z) {
    int i = blockIdx.x * blockDim.x + threadIdx.x;   // over NROWS*DIM/4
    if (i >= NROWS * DIM / 4) return;
    int row = i >> 6;               // 64 float4 per row
    int c4 = (i & 63) * 4;
    float4 v = reinterpret_cast<const float4*>(z)[i];
    __nv_bfloat162 h0 = __float22bfloat162_rn(make_float2(v.x, v.y));
    __nv_bfloat162 h1 = __float22bfloat162_rn(make_float2(v.z, v.w));
    __nv_bfloat162 l0 = __float22bfloat162_rn(make_float2(
        v.x - __bfloat162float(h0.x), v.y - __bfloat162float(h0.y)));
    __nv_bfloat162 l1 = __float22bfloat162_rn(make_float2(
        v.z - __bfloat162float(h1.x), v.w - __bfloat162float(h1.y)));
    __nv_bfloat162* base = reinterpret_cast<__nv_bfloat162*>(&g_A[row * KPACK + c4]);
    base[0] = h0; base[1] = h1;                         // seg0: hi
    base[128] = h0; base[129] = h1;                     // seg1 (+256): hi
    base[256] = l0; base[257] = l1;                     // seg2 (+512): lo
}
__global__ void pack_e_kernel(const float* __restrict__ e) {
    int i = blockIdx.x * blockDim.x + threadIdx.x;   // over KCODES*DIM/4
    if (i >= KCODES * DIM / 4) return;
    int row = i >> 6;
    int c4 = (i & 63) * 4;
    float4 v = reinterpret_cast<const float4*>(e)[i];
    __nv_bfloat162 h0 = __float22bfloat162_rn(make_float2(v.x, v.y));
    __nv_bfloat162 h1 = __float22bfloat162_rn(make_float2(v.z, v.w));
    __nv_bfloat162 l0 = __float22bfloat162_rn(make_float2(
        v.x - __bfloat162float(h0.x), v.y - __bfloat162float(h0.y)));
    __nv_bfloat162 l1 = __float22bfloat162_rn(make_float2(
        v.z - __bfloat162float(h1.x), v.w - __bfloat162float(h1.y)));
    __nv_bfloat162* base = reinterpret_cast<__nv_bfloat162*>(&g_B[row * KPACK + c4]);
    base[0] = h0; base[1] = h1;                         // seg0: hi
    base[128] = l0; base[129] = l1;                     // seg1 (+256): lo
    base[256] = h0; base[257] = h1;                     // seg2 (+512): hi
}

// ---------------- K1: h[k] = 0.5*|e_k|^2 (exact fp32) ----------------
__global__ void h_kernel(const float* __restrict__ emb) {
    int lane = threadIdx.x & 31;
    int n = blockIdx.x * 8 + (threadIdx.x >> 5);
    float s = 0.0f;
#pragma unroll
    for (int j = 0; j < 8; j++) {
        float v = emb[n * DIM + lane + j * 32];
        s += v * v;
    }
#pragma unroll
    for (int off = 16; off; off >>= 1) s += __shfl_down_sync(0xFFFFFFFFu, s, off);
    if (lane == 0) g_h[n] = 0.5f * s;
}

// ---------------- K2: bf16 mma.sync distance + fused argmin ---------------
// CTA tile 256x128, warp grid 4(M)x2(N), warp tile 64x64.
// BK = 64 bf16 (128 bytes) per chunk; K' = 768 -> 12 chunks.
#define BMm 256
#define BNm 128
#define NCHm 12
#define STAGEA 32768            // A: 256 rows x 128B
#define STAGE  49152            // A 32K + B 16K
#define NSTAGE 3
#define SMEM_H 512
#define SMEM_TOT (SMEM_H + NSTAGE * STAGE)   // 147968

__device__ __forceinline__ void issue_chunk(int tid, int m0, int n0, int c,
                                            uint32_t stage_base) {
    const char* Ag = reinterpret_cast<const char*>(g_A);
    const char* Bg = reinterpret_cast<const char*>(g_B);
#pragma unroll
    for (int i = 0; i < 8; i++) {             // A: 256 rows x 8 16B-chunks
        int lin = tid + i * 256;              // 0..2047
        int row = lin >> 3;
        int ch = lin & 7;
        uint32_t sw = (uint32_t)(row * 128 + ((ch ^ (row & 7)) * 16));
        cp_async16(stage_base + sw,
                   Ag + (size_t)(m0 + row) * (KPACK * 2) + c * 128 + ch * 16);
    }
#pragma unroll
    for (int i = 0; i < 4; i++) {             // B: 128 rows x 8 16B-chunks
        int lin = tid + i * 256;              // 0..1023
        int row = lin >> 3;
        int ch = lin & 7;
        uint32_t sw = (uint32_t)(row * 128 + ((ch ^ (row & 7)) * 16));
        cp_async16(stage_base + STAGEA + sw,
                   Bg + (size_t)(n0 + row) * (KPACK * 2) + c * 128 + ch * 16);
    }
}

__global__ void __launch_bounds__(256)
dist_mma_kernel() {
    extern __shared__ char smem[];
    const uint32_t sb = smem_u32(smem);
    const int tid = threadIdx.x;
    const int wid = tid >> 5;
    const int l = tid & 31;
    const int warp_m = wid >> 1;          // 0..3
    const int warp_n = wid & 1;           // 0..1
    const int m0 = blockIdx.y * BMm;
    const int n0 = blockIdx.x * BNm;
    float* hsm = reinterpret_cast<float*>(smem);

    if (tid < 128) hsm[tid] = g_h[n0 + tid];

    float acc[4][8][4];
#pragma unroll
    for (int mi = 0; mi < 4; mi++)
#pragma unroll
        for (int ni = 0; ni < 8; ni++)
#pragma unroll
            for (int f = 0; f < 4; f++) acc[mi][ni][f] = 0.0f;

    // ldmatrix per-lane addressing precompute
    const int a_r = (l & 15);             // row within 16-row A tile
    const int a_half = l >> 4;            // k-half selector (0/1)
    const int b_r = (l & 7) + ((l >> 4) << 3);  // n within 16-col B group
    const int b_half = (l >> 3) & 1;

    issue_chunk(tid, m0, n0, 0, sb + SMEM_H + 0 * STAGE); cp_commit();
    issue_chunk(tid, m0, n0, 1, sb + SMEM_H + 1 * STAGE); cp_commit();

    int stage = 0;
    for (int c = 0; c < NCHm; c++) {
        cp_wait1();
        __syncthreads();
        if (c + 2 < NCHm) {
            int s2 = (stage + 2) % NSTAGE;
            issue_chunk(tid, m0, n0, c + 2, sb + SMEM_H + s2 * STAGE);
            cp_commit();
        }
        const uint32_t As = sb + SMEM_H + stage * STAGE;
        const uint32_t Bs = As + STAGEA;
#pragma unroll
        for (int ks = 0; ks < 4; ks++) {
            uint32_t a[4][4];
#pragma unroll
            for (int mi = 0; mi < 4; mi++) {
                int row = warp_m * 64 + mi * 16 + a_r;
                uint32_t addr = As + row * 128 +
                                (((ks * 2 + a_half) ^ (row & 7)) * 16);
                ldsm4(a[mi][0], a[mi][1], a[mi][2], a[mi][3], addr);
            }
            uint32_t b[8][2];
#pragma unroll
            for (int nb = 0; nb < 4; nb++) {
                int row = warp_n * 64 + nb * 16 + b_r;
                uint32_t addr = Bs + row * 128 +
                                (((ks * 2 + b_half) ^ (row & 7)) * 16);
                uint32_t r0, r1, r2, r3;
                ldsm4(r0, r1, r2, r3, addr);
                b[nb * 2 + 0][0] = r0; b[nb * 2 + 0][1] = r1;
                b[nb * 2 + 1][0] = r2; b[nb * 2 + 1][1] = r3;
            }
#pragma unroll
            for (int mi = 0; mi < 4; mi++)
#pragma unroll
                for (int ni = 0; ni < 8; ni++)
                    mma16816(acc[mi][ni][0], acc[mi][ni][1],
                             acc[mi][ni][2], acc[mi][ni][3],
                             a[mi][0], a[mi][1], a[mi][2], a[mi][3],
                             b[ni][0], b[ni][1]);
        }
        stage = (stage + 1) % NSTAGE;
    }

    // epilogue: s = 0.5|e|^2 - dot ; per-row packed-key argmin
    const int g = l >> 2;                 // row group 0..7
    const int tg = l & 3;                 // col pair selector
#pragma unroll
    for (int mi = 0; mi < 4; mi++) {
        unsigned long long klo = 0xFFFFFFFFFFFFFFFFull;
        unsigned long long khi = 0xFFFFFFFFFFFFFFFFull;
#pragma unroll
        for (int ni = 0; ni < 8; ni++) {
            int col = warp_n * 64 + ni * 8 + 2 * tg;
            float h0 = hsm[col], h1 = hsm[col + 1];
            unsigned int gc = (unsigned int)(n0 + col);
            float s0 = h0 - acc[mi][ni][0];
            float s1 = h1 - acc[mi][ni][1];
            float s2 = h0 - acc[mi][ni][2];
            float s3 = h1 - acc[mi][ni][3];
            klo = ullmin2(klo, ((unsigned long long)fkey(s0) << 32) | gc);
            klo = ullmin2(klo, ((unsigned long long)fkey(s1) << 32) | (gc + 1));
            khi = ullmin2(khi, ((unsigned long long)fkey(s2) << 32) | gc);
            khi = ullmin2(khi, ((unsigned long long)fkey(s3) << 32) | (gc + 1));
        }
        // reduce across the 4 lanes of a quad (same rows, different cols)
#pragma unroll
        for (int off = 1; off <= 2; off <<= 1) {
            klo = ullmin2(klo, __shfl_xor_sync(0xFFFFFFFFu, klo, off));
            khi = ullmin2(khi, __shfl_xor_sync(0xFFFFFFFFu, khi, off));
        }
        if (tg == 0) {
            int row = m0 + warp_m * 64 + mi * 16 + g;
            atomicMin(&g_keys[row], klo);
            atomicMin(&g_keys[row + 8], khi);
        }
    }
}

// ---------------- K3: gather z_q, loss partials, scatter counts/dw -------
// 4 rows per 256-thread block; 64 threads x float4 per row.
__global__ void assign_kernel(const float* __restrict__ z,
                              const float* __restrict__ emb,
                              float* __restrict__ out) {
    int t = threadIdx.x;
    int row = blockIdx.x * 4 + (t >> 6);
    int c = (t & 63) * 4;
    int idx = (int)(g_keys[row] & 0xFFFFFFFFull);
    float4 zv = *reinterpret_cast<const float4*>(&z[row * DIM + c]);
    float4 ev = *reinterpret_cast<const float4*>(&emb[idx * DIM + c]);
    float4 q;
    q.x = zv.x + (ev.x - zv.x);
    q.y = zv.y + (ev.y - zv.y);
    q.z = zv.z + (ev.z - zv.z);
    q.w = zv.w + (ev.w - zv.w);
    *reinterpret_cast<float4*>(&out[ZQ_OFF + row * DIM + c]) = q;
    float dx = ev.x - zv.x, dy = ev.y - zv.y, dz = ev.z - zv.z, dw = ev.w - zv.w;
    float v = dx * dx + dy * dy + dz * dz + dw * dw;
#pragma unroll
    for (int off = 16; off; off >>= 1) v += __shfl_down_sync(0xFFFFFFFFu, v, off);
    __shared__ float red[8];
    if ((t & 31) == 0) red[t >> 5] = v;
    __syncthreads();
    if (t == 0) {
        float s = 0.0f;
#pragma unroll
        for (int w = 0; w < 8; w++) s += red[w];
        atomicAdd(&g_loss_sum, s);
    }
    if ((t & 63) == 0) {
        atomicAdd(&g_counts[idx], 1.0f);
        out[IDX_OFF + row] = (float)idx;
    }
    float* dwp = &g_dw[idx * DIM + c];
    atomicAdd(dwp + 0, zv.x);
    atomicAdd(dwp + 1, zv.y);
    atomicAdd(dwp + 2, zv.z);
    atomicAdd(dwp + 3, zv.w);
}

// ---------------- K4: new_cluster_size + n = sum -------------------------
__global__ void ncs_kernel(const float* __restrict__ ecs, float* __restrict__ out) {
    int t = threadIdx.x;
    float s = 0.0f;
#pragma unroll
    for (int j = 0; j < KCODES / 1024; j++) {
        int k = t + j * 1024;
        float v = ecs[k] * DECAY_F + OMD_F * g_counts[k];
        out[NCS_OFF + k] = v;
        s += v;
    }
#pragma unroll
    for (int off = 16; off; off >>= 1) s += __shfl_down_sync(0xFFFFFFFFu, s, off);
    __shared__ float red[32];
    if ((t & 31) == 0) red[t >> 5] = s;
    __syncthreads();
    if (t == 0) {
        float tot = 0.0f;
#pragma unroll
        for (int w = 0; w < 32; w++) tot += red[w];
        g_n_tot = tot;
    }
}

// ---------------- K5: new_ema_w, new_embedding, loss ---------------------
__global__ void final_kernel(const float* __restrict__ emaw, float* __restrict__ out) {
    int k = blockIdx.x;
    int d = threadIdx.x;
    float ncs = out[NCS_OFF + k];
    float n = g_n_tot;
    float cs = (ncs + EPSV) / (n + (float)KCODES * EPSV) * n;
    int e = k * DIM + d;
    float w = emaw[e] * DECAY_F + OMD_F * g_dw[e];
    out[NEMAW_OFF + e] = w;
    out[NEMB_OFF + e] = w / cs;
    if (k == 0 && d == 0)
        out[LOSS_OFF] = CCOST * g_loss_sum / (float)((long long)NROWS * DIM);
}

// ---------------- launch -------------------------------------------------
extern "C" void kernel_launch(void* const* d_in, const int* in_sizes, int n_in,
                              void* d_out, int out_size) {
    const float* z    = (const float*)d_in[0];
    const float* emb  = (const float*)d_in[1];
    const float* ecs  = (const float*)d_in[2];
    const float* emaw = (const float*)d_in[3];
    float* out = (float*)d_out;

    cudaFuncSetAttribute(dist_mma_kernel,
                         cudaFuncAttributeMaxDynamicSharedMemorySize, SMEM_TOT);

    init_kernel<<<(KCODES * DIM + 255) / 256, 256>>>();
    pack_z_kernel<<<(NROWS * DIM / 4 + 255) / 256, 256>>>(z);
    pack_e_kernel<<<(KCODES * DIM / 4 + 255) / 256, 256>>>(emb);
    h_kernel<<<KCODES / 8, 256>>>(emb);
    dim3 g(KCODES / BNm, NROWS / BMm);
    dist_mma_kernel<<<g, 256, SMEM_TOT>>>();
    assign_kernel<<<NROWS / 4, 256>>>(z, emb, out);
    ncs_kernel<<<1, 1024>>>(ecs, out);
    final_kernel<<<KCODES, DIM>>>(emaw, out);
}

// round 10
// speedup vs baseline: 1.0520x; 1.0520x over previous
#include <cuda_runtime.h>
#include <cuda_bf16.h>
#include <cstdint>

#define NROWS   32768
#define KCODES  8192
#define DIM     256
#define KPACK   768            // 3 * DIM (hi|hi|lo vs hi|lo|hi)
#define DECAY_F 0.99f
#define OMD_F   0.01f
#define EPSV    1e-5f
#define CCOST   0.25f

// output layout (flattened, reference return order, all f32)
#define ZQ_OFF    0
#define LOSS_OFF  8388608
#define IDX_OFF   8388609
#define NEMB_OFF  8421377
#define NCS_OFF   10518529
#define NEMAW_OFF 10526721

// ---------------- scratch (static device globals; no allocs) ----------------
__device__ unsigned long long g_keys[NROWS];
__device__ float g_h[KCODES];
__device__ float g_counts[KCODES];
__device__ float g_dw[KCODES * DIM];
__device__ float g_loss_sum;
__device__ float g_n_tot;
// packed bf16 split operands (K-concatenated)
__device__ __nv_bfloat16 g_A[NROWS * KPACK];    // [z_hi | z_hi | z_lo]
__device__ __nv_bfloat16 g_B[KCODES * KPACK];   // [e_hi | e_lo | e_hi]

// ---------------- helpers ----------------
__device__ __forceinline__ unsigned int fkey(float f) {
    unsigned int u = __float_as_uint(f);
    return (u & 0x80000000u) ? ~u : (u | 0x80000000u);
}
__device__ __forceinline__ unsigned long long ullmin2(unsigned long long a,
                                                      unsigned long long b) {
    return a < b ? a : b;
}
__device__ __forceinline__ uint32_t smem_u32(const void* p) {
    uint32_t a;
    asm("{ .reg .u64 t; cvta.to.shared.u64 t, %1; cvt.u32.u64 %0, t; }"
        : "=r"(a) : "l"(p));
    return a;
}
__device__ __forceinline__ void cp_async16(uint32_t smem, const void* g) {
    asm volatile("cp.async.cg.shared.global [%0], [%1], 16;"
                 :: "r"(smem), "l"(g));
}
__device__ __forceinline__ void cp_commit() {
    asm volatile("cp.async.commit_group;");
}
__device__ __forceinline__ void cp_wait1() {
    asm volatile("cp.async.wait_group 1;");
}
__device__ __forceinline__ void ldsm4(uint32_t& r0, uint32_t& r1, uint32_t& r2,
                                      uint32_t& r3, uint32_t addr) {
    asm volatile("ldmatrix.sync.aligned.m8n8.x4.shared.b16 {%0,%1,%2,%3}, [%4];"
                 : "=r"(r0), "=r"(r1), "=r"(r2), "=r"(r3) : "r"(addr));
}
__device__ __forceinline__ void mma16816(float& c0, float& c1, float& c2, float& c3,
                                         uint32_t a0, uint32_t a1, uint32_t a2,
                                         uint32_t a3, uint32_t b0, uint32_t b1) {
    asm volatile(
        "mma.sync.aligned.m16n8k16.row.col.f32.bf16.bf16.f32 "
        "{%0,%1,%2,%3}, {%4,%5,%6,%7}, {%8,%9}, {%0,%1,%2,%3};"
        : "+f"(c0), "+f"(c1), "+f"(c2), "+f"(c3)
        : "r"(a0), "r"(a1), "r"(a2), "r"(a3), "r"(b0), "r"(b1));
}

// ---------------- K0: zero scratch ----------------
__global__ void init_kernel() {
    int i = blockIdx.x * blockDim.x + threadIdx.x;
    if (i < KCODES * DIM) g_dw[i] = 0.0f;
    if (i < NROWS) g_keys[i] = 0xFFFFFFFFFFFFFFFFull;
    if (i < KCODES) g_counts[i] = 0.0f;
    if (i == 0) g_loss_sum = 0.0f;
}

// ---------------- K0b: bf16 hi/lo split + K-concat pack -------------------
__global__ void pack_z_kernel(const float* __restrict__ z) {
    int i = blockIdx.x * blockDim.x + threadIdx.x;   // over NROWS*DIM/4
    if (i >= NROWS * DIM / 4) return;
    int row = i >> 6;               // 64 float4 per row
    int c4 = (i & 63) * 4;
    float4 v = reinterpret_cast<const float4*>(z)[i];
    __nv_bfloat162 h0 = __float22bfloat162_rn(make_float2(v.x, v.y));
    __nv_bfloat162 h1 = __float22bfloat162_rn(make_float2(v.z, v.w));
    __nv_bfloat162 l0 = __float22bfloat162_rn(make_float2(
        v.x - __bfloat162float(h0.x), v.y - __bfloat162float(h0.y)));
    __nv_bfloat162 l1 = __float22bfloat162_rn(make_float2(
        v.z - __bfloat162float(h1.x), v.w - __bfloat162float(h1.y)));
    __nv_bfloat162* base = reinterpret_cast<__nv_bfloat162*>(&g_A[row * KPACK + c4]);
    base[0] = h0; base[1] = h1;                         // seg0: hi
    base[128] = h0; base[129] = h1;                     // seg1 (+256): hi
    base[256] = l0; base[257] = l1;                     // seg2 (+512): lo
}
__global__ void pack_e_kernel(const float* __restrict__ e) {
    int i = blockIdx.x * blockDim.x + threadIdx.x;   // over KCODES*DIM/4
    if (i >= KCODES * DIM / 4) return;
    int row = i >> 6;
    int c4 = (i & 63) * 4;
    float4 v = reinterpret_cast<const float4*>(e)[i];
    __nv_bfloat162 h0 = __float22bfloat162_rn(make_float2(v.x, v.y));
    __nv_bfloat162 h1 = __float22bfloat162_rn(make_float2(v.z, v.w));
    __nv_bfloat162 l0 = __float22bfloat162_rn(make_float2(
        v.x - __bfloat162float(h0.x), v.y - __bfloat162float(h0.y)));
    __nv_bfloat162 l1 = __float22bfloat162_rn(make_float2(
        v.z - __bfloat162float(h1.x), v.w - __bfloat162float(h1.y)));
    __nv_bfloat162* base = reinterpret_cast<__nv_bfloat162*>(&g_B[row * KPACK + c4]);
    base[0] = h0; base[1] = h1;                         // seg0: hi
    base[128] = l0; base[129] = l1;                     // seg1 (+256): lo
    base[256] = h0; base[257] = h1;                     // seg2 (+512): hi
}

// ---------------- K1: h[k] = 0.5*|e_k|^2 (exact fp32) ----------------
__global__ void h_kernel(const float* __restrict__ emb) {
    int lane = threadIdx.x & 31;
    int n = blockIdx.x * 8 + (threadIdx.x >> 5);
    float s = 0.0f;
#pragma unroll
    for (int j = 0; j < 8; j++) {
        float v = emb[n * DIM + lane + j * 32];
        s += v * v;
    }
#pragma unroll
    for (int off = 16; off; off >>= 1) s += __shfl_down_sync(0xFFFFFFFFu, s, off);
    if (lane == 0) g_h[n] = 0.5f * s;
}

// ---------------- K2: bf16 mma.sync distance + fused argmin ---------------
// CTA tile 256x128, 512 threads, warp grid 4(M)x4(N), warp tile 64x32.
// BK = 64 bf16 (128 bytes) per chunk; K' = 768 -> 12 chunks.
#define BMm 256
#define BNm 128
#define NCHm 12
#define STAGEA 32768            // A: 256 rows x 128B
#define STAGE  49152            // A 32K + B 16K
#define NSTAGE 3
#define SMEM_H 512
#define SMEM_TOT (SMEM_H + NSTAGE * STAGE)   // 147968

__device__ __forceinline__ void issue_chunk(int tid, int m0, int n0, int c,
                                            uint32_t stage_base) {
    const char* Ag = reinterpret_cast<const char*>(g_A);
    const char* Bg = reinterpret_cast<const char*>(g_B);
#pragma unroll
    for (int i = 0; i < 4; i++) {             // A: 256 rows x 8 16B-chunks
        int lin = tid + i * 512;              // 0..2047
        int row = lin >> 3;
        int ch = lin & 7;
        uint32_t sw = (uint32_t)(row * 128 + ((ch ^ (row & 7)) * 16));
        cp_async16(stage_base + sw,
                   Ag + (size_t)(m0 + row) * (KPACK * 2) + c * 128 + ch * 16);
    }
#pragma unroll
    for (int i = 0; i < 2; i++) {             // B: 128 rows x 8 16B-chunks
        int lin = tid + i * 512;              // 0..1023
        int row = lin >> 3;
        int ch = lin & 7;
        uint32_t sw = (uint32_t)(row * 128 + ((ch ^ (row & 7)) * 16));
        cp_async16(stage_base + STAGEA + sw,
                   Bg + (size_t)(n0 + row) * (KPACK * 2) + c * 128 + ch * 16);
    }
}

__global__ void __launch_bounds__(512, 1)
dist_mma_kernel() {
    extern __shared__ char smem[];
    const uint32_t sb = smem_u32(smem);
    const int tid = threadIdx.x;
    const int wid = tid >> 5;
    const int l = tid & 31;
    const int warp_m = wid >> 2;          // 0..3  (64 rows each)
    const int warp_n = wid & 3;           // 0..3  (32 cols each)
    const int m0 = blockIdx.y * BMm;
    const int n0 = blockIdx.x * BNm;
    float* hsm = reinterpret_cast<float*>(smem);

    if (tid < 128) hsm[tid] = g_h[n0 + tid];

    float acc[4][4][4];
#pragma unroll
    for (int mi = 0; mi < 4; mi++)
#pragma unroll
        for (int ni = 0; ni < 4; ni++)
#pragma unroll
            for (int f = 0; f < 4; f++) acc[mi][ni][f] = 0.0f;

    // ldmatrix per-lane addressing precompute
    const int a_r = (l & 15);             // row within 16-row A tile
    const int a_half = l >> 4;            // k-half selector (0/1)
    const int b_r = (l & 7) + ((l >> 4) << 3);  // n within 16-col B group
    const int b_half = (l >> 3) & 1;

    issue_chunk(tid, m0, n0, 0, sb + SMEM_H + 0 * STAGE); cp_commit();
    issue_chunk(tid, m0, n0, 1, sb + SMEM_H + 1 * STAGE); cp_commit();

    int stage = 0;
    for (int c = 0; c < NCHm; c++) {
        cp_wait1();
        __syncthreads();
        if (c + 2 < NCHm) {
            int s2 = (stage + 2) % NSTAGE;
            issue_chunk(tid, m0, n0, c + 2, sb + SMEM_H + s2 * STAGE);
            cp_commit();
        }
        const uint32_t As = sb + SMEM_H + stage * STAGE;
        const uint32_t Bs = As + STAGEA;
#pragma unroll
        for (int ks = 0; ks < 4; ks++) {
            uint32_t a[4][4];
#pragma unroll
            for (int mi = 0; mi < 4; mi++) {
                int row = warp_m * 64 + mi * 16 + a_r;
                uint32_t addr = As + row * 128 +
                                (((ks * 2 + a_half) ^ (row & 7)) * 16);
                ldsm4(a[mi][0], a[mi][1], a[mi][2], a[mi][3], addr);
            }
            uint32_t b[4][2];
#pragma unroll
            for (int nb = 0; nb < 2; nb++) {
                int row = warp_n * 32 + nb * 16 + b_r;
                uint32_t addr = Bs + row * 128 +
                                (((ks * 2 + b_half) ^ (row & 7)) * 16);
                uint32_t r0, r1, r2, r3;
                ldsm4(r0, r1, r2, r3, addr);
                b[nb * 2 + 0][0] = r0; b[nb * 2 + 0][1] = r1;
                b[nb * 2 + 1][0] = r2; b[nb * 2 + 1][1] = r3;
            }
#pragma unroll
            for (int mi = 0; mi < 4; mi++)
#pragma unroll
                for (int ni = 0; ni < 4; ni++)
                    mma16816(acc[mi][ni][0], acc[mi][ni][1],
                             acc[mi][ni][2], acc[mi][ni][3],
                             a[mi][0], a[mi][1], a[mi][2], a[mi][3],
                             b[ni][0], b[ni][1]);
        }
        stage = (stage + 1) % NSTAGE;
    }

    // epilogue: s = 0.5|e|^2 - dot ; per-row packed-key argmin
    const int g = l >> 2;                 // row group 0..7
    const int tg = l & 3;                 // col pair selector
#pragma unroll
    for (int mi = 0; mi < 4; mi++) {
        unsigned long long klo = 0xFFFFFFFFFFFFFFFFull;
        unsigned long long khi = 0xFFFFFFFFFFFFFFFFull;
#pragma unroll
        for (int ni = 0; ni < 4; ni++) {
            int col = warp_n * 32 + ni * 8 + 2 * tg;
            float h0 = hsm[col], h1 = hsm[col + 1];
            unsigned int gc = (unsigned int)(n0 + col);
            float s0 = h0 - acc[mi][ni][0];
            float s1 = h1 - acc[mi][ni][1];
            float s2 = h0 - acc[mi][ni][2];
            float s3 = h1 - acc[mi][ni][3];
            klo = ullmin2(klo, ((unsigned long long)fkey(s0) << 32) | gc);
            klo = ullmin2(klo, ((unsigned long long)fkey(s1) << 32) | (gc + 1));
            khi = ullmin2(khi, ((unsigned long long)fkey(s2) << 32) | gc);
            khi = ullmin2(khi, ((unsigned long long)fkey(s3) << 32) | (gc + 1));
        }
        // reduce across the 4 lanes of a quad (same rows, different cols)
#pragma unroll
        for (int off = 1; off <= 2; off <<= 1) {
            klo = ullmin2(klo, __shfl_xor_sync(0xFFFFFFFFu, klo, off));
            khi = ullmin2(khi, __shfl_xor_sync(0xFFFFFFFFu, khi, off));
        }
        if (tg == 0) {
            int row = m0 + warp_m * 64 + mi * 16 + g;
            atomicMin(&g_keys[row], klo);
            atomicMin(&g_keys[row + 8], khi);
        }
    }
}

// ---------------- K3: gather z_q, loss partials, scatter counts/dw -------
// 4 rows per 256-thread block; 64 threads x float4 per row.
__global__ void assign_kernel(const float* __restrict__ z,
                              const float* __restrict__ emb,
                              float* __restrict__ out) {
    int t = threadIdx.x;
    int row = blockIdx.x * 4 + (t >> 6);
    int c = (t & 63) * 4;
    int idx = (int)(g_keys[row] & 0xFFFFFFFFull);
    float4 zv = *reinterpret_cast<const float4*>(&z[row * DIM + c]);
    float4 ev = *reinterpret_cast<const float4*>(&emb[idx * DIM + c]);
    float4 q;
    q.x = zv.x + (ev.x - zv.x);
    q.y = zv.y + (ev.y - zv.y);
    q.z = zv.z + (ev.z - zv.z);
    q.w = zv.w + (ev.w - zv.w);
    *reinterpret_cast<float4*>(&out[ZQ_OFF + row * DIM + c]) = q;
    float dx = ev.x - zv.x, dy = ev.y - zv.y, dz = ev.z - zv.z, dw = ev.w - zv.w;
    float v = dx * dx + dy * dy + dz * dz + dw * dw;
#pragma unroll
    for (int off = 16; off; off >>= 1) v += __shfl_down_sync(0xFFFFFFFFu, v, off);
    __shared__ float red[8];
    if ((t & 31) == 0) red[t >> 5] = v;
    __syncthreads();
    if (t == 0) {
        float s = 0.0f;
#pragma unroll
        for (int w = 0; w < 8; w++) s += red[w];
        atomicAdd(&g_loss_sum, s);
    }
    if ((t & 63) == 0) {
        atomicAdd(&g_counts[idx], 1.0f);
        out[IDX_OFF + row] = (float)idx;
    }
    float* dwp = &g_dw[idx * DIM + c];
    atomicAdd(dwp + 0, zv.x);
    atomicAdd(dwp + 1, zv.y);
    atomicAdd(dwp + 2, zv.z);
    atomicAdd(dwp + 3, zv.w);
}

// ---------------- K4: new_cluster_size + n = sum -------------------------
__global__ void ncs_kernel(const float* __restrict__ ecs, float* __restrict__ out) {
    int t = threadIdx.x;
    float s = 0.0f;
#pragma unroll
    for (int j = 0; j < KCODES / 1024; j++) {
        int k = t + j * 1024;
        float v = ecs[k] * DECAY_F + OMD_F * g_counts[k];
        out[NCS_OFF + k] = v;
        s += v;
    }
#pragma unroll
    for (int off = 16; off; off >>= 1) s += __shfl_down_sync(0xFFFFFFFFu, s, off);
    __shared__ float red[32];
    if ((t & 31) == 0) red[t >> 5] = s;
    __syncthreads();
    if (t == 0) {
        float tot = 0.0f;
#pragma unroll
        for (int w = 0; w < 32; w++) tot += red[w];
        g_n_tot = tot;
    }
}

// ---------------- K5: new_ema_w, new_embedding, loss ---------------------
__global__ void final_kernel(const float* __restrict__ emaw, float* __restrict__ out) {
    int k = blockIdx.x;
    int d = threadIdx.x;
    float ncs = out[NCS_OFF + k];
    float n = g_n_tot;
    float cs = (ncs + EPSV) / (n + (float)KCODES * EPSV) * n;
    int e = k * DIM + d;
    float w = emaw[e] * DECAY_F + OMD_F * g_dw[e];
    out[NEMAW_OFF + e] = w;
    out[NEMB_OFF + e] = w / cs;
    if (k == 0 && d == 0)
        out[LOSS_OFF] = CCOST * g_loss_sum / (float)((long long)NROWS * DIM);
}

// ---------------- launch -------------------------------------------------
extern "C" void kernel_launch(void* const* d_in, const int* in_sizes, int n_in,
                              void* d_out, int out_size) {
    const float* z    = (const float*)d_in[0];
    const float* emb  = (const float*)d_in[1];
    const float* ecs  = (const float*)d_in[2];
    const float* emaw = (const float*)d_in[3];
    float* out = (float*)d_out;

    cudaFuncSetAttribute(dist_mma_kernel,
                         cudaFuncAttributeMaxDynamicSharedMemorySize, SMEM_TOT);

    init_kernel<<<(KCODES * DIM + 255) / 256, 256>>>();
    pack_z_kernel<<<(NROWS * DIM / 4 + 255) / 256, 256>>>(z);
    pack_e_kernel<<<(KCODES * DIM / 4 + 255) / 256, 256>>>(emb);
    h_kernel<<<KCODES / 8, 256>>>(emb);
    dim3 g(KCODES / BNm, NROWS / BMm);
    dist_mma_kernel<<<g, 512, SMEM_TOT>>>();
    assign_kernel<<<NROWS / 4, 256>>>(z, emb, out);
    ncs_kernel<<<1, 1024>>>(ecs, out);
    final_kernel<<<KCODES, DIM>>>(emaw, out);
}